// round 1
// baseline (speedup 1.0000x reference)
#include <cuda_runtime.h>
#include <float.h>

#define S_TILE   128
#define K_CHUNK  128
#define NBLOCKS  1024          // (32*64*64)/128
#define SMEM_BYTES (2*64*128*4 + 128*4 + 128*4)   // 66560

__device__ float  g_cbT[64 * 1024];   // [c][k]
__device__ float  g_esq[1024];
__device__ double g_part[NBLOCKS];

// Transpose codebook -> [c][k] and precompute e_sq (square-then-add, matching
// jnp.sum(codebook*codebook, axis=1) elementwise-square semantics).
__global__ void vq_prep(const float* __restrict__ cb) {
    int tid = blockIdx.x * 256 + threadIdx.x;
    if (tid < 65536) {
        int k = tid >> 6, c = tid & 63;
        g_cbT[c * 1024 + k] = cb[tid];
    }
    if (tid < 1024) {
        const float* row = cb + tid * 64;
        float s = 0.f;
        #pragma unroll
        for (int c = 0; c < 64; ++c)
            s = __fadd_rn(s, __fmul_rn(row[c], row[c]));
        g_esq[tid] = s;
    }
}

__global__ void __launch_bounds__(256, 2)
vq_main(const float* __restrict__ x, const float* __restrict__ cb,
        float* __restrict__ out) {
    extern __shared__ float smem[];
    float* xs     = smem;                  // [64][128] x tile, c-major
    float* es     = smem + 8192;           // [64][128] codebook chunk, c-major
    float* xsq_sh = smem + 16384;          // [128]
    int*   idx_sh = (int*)(smem + 16512);  // [128]
    float* rmv    = es;                    // reuse es after mainloop: [16][128]
    int*   rmk    = (int*)(es + 2048);     // [16][128]

    const int tid = threadIdx.x;
    const int tx  = tid & 15;     // spatial group
    const int ty  = tid >> 4;     // code group
    const int R   = blockIdx.x * S_TILE;
    const int b   = R >> 12;
    const int sb  = R & 4095;
    const float* xbase = x + (size_t)b * 262144 + sb;

    // Load x tile: 64 channels x 128 spatial (contiguous per channel)
    #pragma unroll
    for (int i = 0; i < 8; ++i) {
        int lin = i * 256 + tid;
        int c   = lin >> 5;
        int f4  = (lin & 31) << 2;
        *(float4*)(xs + c * 128 + f4) =
            *(const float4*)(xbase + (size_t)c * 4096 + f4);
    }
    __syncthreads();

    // x_sq per spatial row: sequential over c, square-then-add (matches ref)
    if (tid < 128) {
        float s = 0.f;
        #pragma unroll
        for (int c = 0; c < 64; ++c) {
            float v = xs[c * 128 + tid];
            s = __fadd_rn(s, __fmul_rn(v, v));
        }
        xsq_sh[tid] = s;
    }
    __syncthreads();

    float xsq[8];
    #pragma unroll
    for (int i = 0; i < 8; ++i) {
        int sl = (i < 4) ? (tx * 4 + i) : (64 + tx * 4 + i - 4);
        xsq[i] = xsq_sh[sl];
    }

    float minv[8]; int mink[8];
    #pragma unroll
    for (int i = 0; i < 8; ++i) { minv[i] = FLT_MAX; mink[i] = 0; }

    for (int chunk = 0; chunk < 8; ++chunk) {
        const int k0 = chunk * K_CHUNK;
        // Load codebook chunk from transposed copy (conflict-free)
        #pragma unroll
        for (int i = 0; i < 8; ++i) {
            int lin = i * 256 + tid;
            int c   = lin >> 5;
            int f4  = (lin & 31) << 2;
            *(float4*)(es + c * 128 + f4) =
                *(const float4*)(g_cbT + c * 1024 + k0 + f4);
        }
        __syncthreads();

        float acc[8][8];
        #pragma unroll
        for (int i = 0; i < 8; ++i)
            #pragma unroll
            for (int j = 0; j < 8; ++j) acc[i][j] = 0.f;

        #pragma unroll 8
        for (int c = 0; c < 64; ++c) {
            float a[8], bb[8];
            *(float4*)(a)      = *(float4*)(xs + c * 128 + tx * 4);
            *(float4*)(a + 4)  = *(float4*)(xs + c * 128 + 64 + tx * 4);
            *(float4*)(bb)     = *(float4*)(es + c * 128 + ty * 4);
            *(float4*)(bb + 4) = *(float4*)(es + c * 128 + 64 + ty * 4);
            #pragma unroll
            for (int i = 0; i < 8; ++i)
                #pragma unroll
                for (int j = 0; j < 8; ++j)
                    acc[i][j] = __fmaf_rn(a[i], bb[j], acc[i][j]);
        }

        // Score: d2 = (x_sq + e_sq) - 2*dot, exact rounding order of reference
        #pragma unroll
        for (int j = 0; j < 8; ++j) {
            int kl = (j < 4) ? (ty * 4 + j) : (64 + ty * 4 + j - 4);
            int kg = k0 + kl;                 // strictly increasing per thread
            float esq = __ldg(g_esq + kg);
            #pragma unroll
            for (int i = 0; i < 8; ++i) {
                float t1 = __fadd_rn(xsq[i], esq);
                float d2 = __fsub_rn(t1, __fmul_rn(2.0f, acc[i][j]));
                if (d2 < minv[i]) { minv[i] = d2; mink[i] = kg; }
            }
        }
        __syncthreads();   // protects es before next chunk load / rmv reuse
    }

    // Cross-thread argmin reduction (16 code-groups per spatial row)
    #pragma unroll
    for (int i = 0; i < 8; ++i) {
        int sl = (i < 4) ? (tx * 4 + i) : (64 + tx * 4 + i - 4);
        rmv[ty * 128 + sl] = minv[i];
        rmk[ty * 128 + sl] = mink[i];
    }
    __syncthreads();
    if (tid < 128) {
        float bv = rmv[tid]; int bk = rmk[tid];
        #pragma unroll
        for (int t = 1; t < 16; ++t) {
            float v = rmv[t * 128 + tid];
            int  k  = rmk[t * 128 + tid];
            if (v < bv || (v == bv && k < bk)) { bv = v; bk = k; }
        }
        idx_sh[tid] = bk;
    }
    __syncthreads();

    // Epilogue: gather codebook rows, write z_q (coalesced per channel),
    // accumulate squared diff deterministically.
    float fsum = 0.f;
    const size_t obase = (size_t)b * 262144 + sb;
    #pragma unroll
    for (int it = 0; it < 32; ++it) {
        int lin = it * 256 + tid;
        int c   = lin >> 7;
        int s   = lin & 127;
        float q = __ldg(cb + idx_sh[s] * 64 + c);
        out[obase + (size_t)c * 4096 + s] = q;
        float d = xs[c * 128 + s] - q;
        fsum = __fmaf_rn(d, d, fsum);
    }
    __syncthreads();
    rmv[tid] = fsum;
    __syncthreads();
    for (int off = 128; off > 0; off >>= 1) {
        if (tid < off) rmv[tid] = __fadd_rn(rmv[tid], rmv[tid + off]);
        __syncthreads();
    }
    if (tid == 0) g_part[blockIdx.x] = (double)rmv[0];
}

__global__ void vq_loss(float* loss_out) {
    __shared__ double sh[256];
    double s = 0.0;
    for (int i = threadIdx.x; i < NBLOCKS; i += 256) s += g_part[i];
    sh[threadIdx.x] = s;
    __syncthreads();
    for (int off = 128; off > 0; off >>= 1) {
        if (threadIdx.x < off) sh[threadIdx.x] += sh[threadIdx.x + off];
        __syncthreads();
    }
    if (threadIdx.x == 0) {
        float m = (float)(sh[0] / 8388608.0);
        loss_out[0] = __fadd_rn(m, __fmul_rn(0.25f, m));  // mse + 0.25*mse
    }
}

extern "C" void kernel_launch(void* const* d_in, const int* in_sizes, int n_in,
                              void* d_out, int out_size) {
    const float* x  = (const float*)d_in[0];
    const float* cb = (const float*)d_in[1];
    float* out = (float*)d_out;

    cudaFuncSetAttribute(vq_main, cudaFuncAttributeMaxDynamicSharedMemorySize,
                         SMEM_BYTES);
    vq_prep<<<256, 256>>>(cb);
    vq_main<<<NBLOCKS, 256, SMEM_BYTES>>>(x, cb, out);
    vq_loss<<<1, 256>>>(out + (out_size - 1));
}